// round 1
// baseline (speedup 1.0000x reference)
#include <cuda_runtime.h>

// ---------------------------------------------------------------------------
// att_conv_normalize_free: fused 1x1-conv attention gate + 3-layer 1x1 conv MLP
// B=16, H=W=256 (65536 px/batch), IN_C=64, mid=32, tail 32->16->8->16.
//
// Strategy (round 1): one thread per pixel. Weights staged (transposed) in
// SMEM, read as LDS.128 broadcasts. All dot products use packed fma.rn.f32x2
// (2 FMAs/instr) which ptxas never emits from C++ — inline PTX required.
// ---------------------------------------------------------------------------

typedef unsigned long long u64;

__device__ __forceinline__ u64 pk2(float lo, float hi) {
    u64 r;
    asm("mov.b64 %0, {%1, %2};" : "=l"(r) : "f"(lo), "f"(hi));
    return r;
}
__device__ __forceinline__ void up2(u64 v, float& lo, float& hi) {
    asm("mov.b64 {%0, %1}, %2;" : "=f"(lo), "=f"(hi) : "l"(v));
}
// d = a * b + d   (packed f32x2)
__device__ __forceinline__ void fma2(u64& d, u64 a, u64 b) {
    asm("fma.rn.f32x2 %0, %1, %2, %0;" : "+l"(d) : "l"(a), "l"(b));
}

__global__ void __launch_bounds__(128)
att_fused_kernel(const float* __restrict__ kv,  const float* __restrict__ qin,
                 const float* __restrict__ kw,  const float* __restrict__ kb,
                 const float* __restrict__ vw,  const float* __restrict__ vb,
                 const float* __restrict__ qw,  const float* __restrict__ qb,
                 const float* __restrict__ scp,
                 const float* __restrict__ d1w, const float* __restrict__ d2w,
                 const float* __restrict__ d3w, const float* __restrict__ d3b,
                 float* __restrict__ out)
{
    // Transposed weight tiles so the c-loop reads contiguous rows.
    __shared__ __align__(16) float s_wkv[64 * 64];  // [c][o]: o<32 key, o>=32 value
    __shared__ __align__(16) float s_wq [64 * 32];  // [c][o]
    __shared__ __align__(16) float s_d1 [16 * 32];  // row-major as given
    __shared__ __align__(16) float s_d2 [ 8 * 16];
    __shared__ __align__(16) float s_d3 [16 *  8];
    __shared__ float s_kb[32], s_vb[32], s_qb[32], s_d3b[16];

    const int tid = threadIdx.x;

    for (int i = tid; i < 64 * 64; i += 128) {
        int o = i & 63, c = i >> 6;
        s_wkv[i] = (o < 32) ? kw[o * 64 + c] : vw[(o - 32) * 64 + c];
    }
    for (int i = tid; i < 64 * 32; i += 128) {
        int o = i & 31, c = i >> 5;
        s_wq[i] = qw[o * 64 + c];
    }
    for (int i = tid; i < 16 * 32; i += 128) s_d1[i] = d1w[i];
    if (tid < 128) { s_d2[tid] = d2w[tid]; s_d3[tid] = d3w[tid]; }
    if (tid < 32)  { s_kb[tid] = kb[tid]; s_vb[tid] = vb[tid]; s_qb[tid] = qb[tid]; }
    if (tid < 16)  { s_d3b[tid] = d3b[tid]; }
    __syncthreads();

    const int g = blockIdx.x * 128 + tid;      // global pixel id, < 1048576
    const int b = g >> 16;                     // batch
    const int p = g & 65535;                   // pixel within plane
    const float* kvp = kv  + ((size_t)b << 22) + p;   // b*64*65536
    const float* qp  = qin + ((size_t)b << 22) + p;
    const float  sc  = __ldg(scp);

    // ---- key / value projections (shared input) ----
    u64 aK[16], aV[16];
#pragma unroll
    for (int i = 0; i < 16; i++) { aK[i] = 0ull; aV[i] = 0ull; }

#pragma unroll 4
    for (int c = 0; c < 64; c++) {
        float xv = __ldcs(kvp + ((size_t)c << 16));
        u64 xx = pk2(xv, xv);
        const ulonglong2* wr = reinterpret_cast<const ulonglong2*>(s_wkv + (c << 6));
#pragma unroll
        for (int i = 0; i < 8; i++) {       // key weights: floats [0,32)
            ulonglong2 w = wr[i];
            fma2(aK[2 * i],     w.x, xx);
            fma2(aK[2 * i + 1], w.y, xx);
        }
#pragma unroll
        for (int i = 0; i < 8; i++) {       // value weights: floats [32,64)
            ulonglong2 w = wr[8 + i];
            fma2(aV[2 * i],     w.x, xx);
            fma2(aV[2 * i + 1], w.y, xx);
        }
    }

    // ---- query projection ----
    u64 aQ[16];
#pragma unroll
    for (int i = 0; i < 16; i++) aQ[i] = 0ull;

#pragma unroll 4
    for (int c = 0; c < 64; c++) {
        float xv = __ldcs(qp + ((size_t)c << 16));
        u64 xx = pk2(xv, xv);
        const ulonglong2* wr = reinterpret_cast<const ulonglong2*>(s_wq + (c << 5));
#pragma unroll
        for (int i = 0; i < 8; i++) {
            ulonglong2 w = wr[i];
            fma2(aQ[2 * i],     w.x, xx);
            fma2(aQ[2 * i + 1], w.y, xx);
        }
    }

    // ---- unpack + bias + sigmoid gate ----
    float x_[32];
#pragma unroll
    for (int j = 0; j < 16; j++) {
        float k0, k1, v0, v1, q0, q1;
        up2(aK[j], k0, k1);
        up2(aV[j], v0, v1);
        up2(aQ[j], q0, q1);
        int o = 2 * j;
        k0 += s_kb[o];     k1 += s_kb[o + 1];
        v0 += s_vb[o];     v1 += s_vb[o + 1];
        q0 += s_qb[o];     q1 += s_qb[o + 1];
        float t0 = k0 * q0 * sc;
        float t1 = k1 * q1 * sc;
        float a0 = __fdividef(1.0f, 1.0f + __expf(-t0));
        float a1 = __fdividef(1.0f, 1.0f + __expf(-t1));
        x_[o]     = a0 * v0;
        x_[o + 1] = a1 * v1;
    }

    u64 xp[16];
#pragma unroll
    for (int j = 0; j < 16; j++) xp[j] = pk2(x_[2 * j], x_[2 * j + 1]);

    // ---- d1: 32 -> 16, relu, no bias ----
    float h1[16];
#pragma unroll
    for (int j = 0; j < 16; j++) {
        u64 a = 0ull;
        const ulonglong2* r = reinterpret_cast<const ulonglong2*>(s_d1 + j * 32);
#pragma unroll
        for (int i = 0; i < 8; i++) {
            ulonglong2 w = r[i];
            fma2(a, w.x, xp[2 * i]);
            fma2(a, w.y, xp[2 * i + 1]);
        }
        float lo, hi; up2(a, lo, hi);
        h1[j] = fmaxf(lo + hi, 0.0f);
    }

    u64 hp[8];
#pragma unroll
    for (int j = 0; j < 8; j++) hp[j] = pk2(h1[2 * j], h1[2 * j + 1]);

    // ---- d2: 16 -> 8, relu, no bias ----
    float h2[8];
#pragma unroll
    for (int j = 0; j < 8; j++) {
        u64 a = 0ull;
        const ulonglong2* r = reinterpret_cast<const ulonglong2*>(s_d2 + j * 16);
#pragma unroll
        for (int i = 0; i < 4; i++) {
            ulonglong2 w = r[i];
            fma2(a, w.x, hp[2 * i]);
            fma2(a, w.y, hp[2 * i + 1]);
        }
        float lo, hi; up2(a, lo, hi);
        h2[j] = fmaxf(lo + hi, 0.0f);
    }

    u64 gp[4];
#pragma unroll
    for (int j = 0; j < 4; j++) gp[j] = pk2(h2[2 * j], h2[2 * j + 1]);

    // ---- d3: 8 -> 16, bias, no act; write out ----
    float* op = out + ((size_t)b << 20) + p;   // b*16*65536
#pragma unroll
    for (int o = 0; o < 16; o++) {
        u64 a = 0ull;
        const ulonglong2* r = reinterpret_cast<const ulonglong2*>(s_d3 + o * 8);
        ulonglong2 w0 = r[0];
        ulonglong2 w1 = r[1];
        fma2(a, w0.x, gp[0]);
        fma2(a, w0.y, gp[1]);
        fma2(a, w1.x, gp[2]);
        fma2(a, w1.y, gp[3]);
        float lo, hi; up2(a, lo, hi);
        __stcs(op + ((size_t)o << 16), lo + hi + s_d3b[o]);
    }
}

extern "C" void kernel_launch(void* const* d_in, const int* in_sizes, int n_in,
                              void* d_out, int out_size)
{
    const float* kv  = (const float*)d_in[0];   // key_value_input [16,64,256,256]
    const float* qin = (const float*)d_in[1];   // query_input     [16,64,256,256]
    const float* kw  = (const float*)d_in[2];   // key_w  [32,64]
    const float* kb  = (const float*)d_in[3];   // key_b  [32]
    const float* vw  = (const float*)d_in[4];   // value_w[32,64]
    const float* vb  = (const float*)d_in[5];   // value_b[32]
    const float* qw  = (const float*)d_in[6];   // query_w[32,64]
    const float* qb  = (const float*)d_in[7];   // query_b[32]
    const float* sc  = (const float*)d_in[8];   // scale [1]
    const float* d1w = (const float*)d_in[9];   // [16,32]
    const float* d2w = (const float*)d_in[10];  // [8,16]
    const float* d3w = (const float*)d_in[11];  // [16,8]
    const float* d3b = (const float*)d_in[12];  // [16]
    float* out = (float*)d_out;                 // [16,16,256,256]

    const int total_px = 16 * 256 * 256;        // 1048576
    att_fused_kernel<<<total_px / 128, 128>>>(kv, qin, kw, kb, vw, vb, qw, qb,
                                              sc, d1w, d2w, d3w, d3b, out);
}

// round 2
// speedup vs baseline: 2.4105x; 2.4105x over previous
#include <cuda_runtime.h>

// ---------------------------------------------------------------------------
// Round 2: SGEMM-style register-blocked fusion.
// Block = 128 threads (4 warps), pixel tile = 256.
// Warp ty owns outputs [ty*8, ty*8+8) (4 f32x2 o-pairs); lane tx owns pixels
// {tx + 32p, p=0..7}. Phases: K -> Q -> sigmoid gate -> V -> smem exchange ->
// per-pixel tail MLP (32->16->8->16). All dot products use fma.rn.f32x2.
// ---------------------------------------------------------------------------

typedef unsigned long long u64;

__device__ __forceinline__ u64 pk2(float lo, float hi) {
    u64 r; asm("mov.b64 %0, {%1, %2};" : "=l"(r) : "f"(lo), "f"(hi)); return r;
}
__device__ __forceinline__ void up2(u64 v, float& lo, float& hi) {
    asm("mov.b64 {%0, %1}, %2;" : "=f"(lo), "=f"(hi) : "l"(v));
}
__device__ __forceinline__ void fma2(u64& d, u64 a, u64 b) {
    asm("fma.rn.f32x2 %0, %1, %2, %0;" : "+l"(d) : "l"(a), "l"(b));
}

// dynamic smem layout (bytes)
#define OFF_X    0          // float sX[64*256]            = 65536
#define OFF_WK   65536      // u64 sWk[64*16]              =  8192
#define OFF_WV   73728      // u64 sWv[64*16]              =  8192
#define OFF_WQ   81920      // u64 sWq[64*16]              =  8192
#define OFF_D1   90112      // u64 sD1[32*8]               =  2048
#define OFF_D2   92160      // u64 sD2[16*4]               =   512
#define OFF_D3   92672      // u64 sD3[8*8]                =   512
#define OFF_KB   93184      // float[32]
#define OFF_VB   93312
#define OFF_QB   93440
#define OFF_D3B  93568      // float[16]
#define SMEM_TOTAL 93696

__device__ __forceinline__ void load_tile(float* sX, const float* src, int tid) {
#pragma unroll
    for (int k = 0; k < 32; k++) {
        int idx = tid + 128 * k;            // float4 index 0..4095
        int c   = idx >> 6;
        int col = idx & 63;
        float4 v = *((const float4*)(src + ((size_t)c << 16)) + col);
        *(float4*)(sX + c * 256 + col * 4) = v;
    }
}

__device__ __forceinline__ void proj_phase(const float* sX, const u64* W,
                                           int tx, int ty, u64 acc[4][8]) {
#pragma unroll 4
    for (int c = 0; c < 64; c++) {
        const float* xr = sX + c * 256 + tx;
        u64 xd[8];
#pragma unroll
        for (int p = 0; p < 8; p++) { float t = xr[32 * p]; xd[p] = pk2(t, t); }
        ulonglong2 wA = *(const ulonglong2*)(W + c * 16 + ty * 4);
        ulonglong2 wB = *(const ulonglong2*)(W + c * 16 + ty * 4 + 2);
        u64 w0 = wA.x, w1 = wA.y, w2 = wB.x, w3 = wB.y;
#pragma unroll
        for (int p = 0; p < 8; p++) {
            fma2(acc[0][p], w0, xd[p]);
            fma2(acc[1][p], w1, xd[p]);
            fma2(acc[2][p], w2, xd[p]);
            fma2(acc[3][p], w3, xd[p]);
        }
    }
}

__global__ void __launch_bounds__(128, 2)
att_fused_kernel(const float* __restrict__ kv,  const float* __restrict__ qin,
                 const float* __restrict__ kw,  const float* __restrict__ kb,
                 const float* __restrict__ vw,  const float* __restrict__ vb,
                 const float* __restrict__ qw,  const float* __restrict__ qb,
                 const float* __restrict__ scp,
                 const float* __restrict__ d1w, const float* __restrict__ d2w,
                 const float* __restrict__ d3w, const float* __restrict__ d3b,
                 float* __restrict__ out)
{
    extern __shared__ char smem[];
    float* sX  = (float*)(smem + OFF_X);
    u64*   sWk = (u64*)(smem + OFF_WK);
    u64*   sWv = (u64*)(smem + OFF_WV);
    u64*   sWq = (u64*)(smem + OFF_WQ);
    u64*   sD1 = (u64*)(smem + OFF_D1);
    u64*   sD2 = (u64*)(smem + OFF_D2);
    u64*   sD3 = (u64*)(smem + OFF_D3);
    float* sKb = (float*)(smem + OFF_KB);
    float* sVb = (float*)(smem + OFF_VB);
    float* sQb = (float*)(smem + OFF_QB);
    float* sD3b= (float*)(smem + OFF_D3B);

    const int tid = threadIdx.x;
    const int ty  = tid >> 5;          // warp id: output group
    const int tx  = tid & 31;          // lane: pixel group

    // ---- stage weights, transposed + f32x2 output-paired ----
    for (int i = tid; i < 64 * 16; i += 128) {
        int c = i >> 4, op = i & 15;
        sWk[i] = pk2(kw[(2 * op) * 64 + c], kw[(2 * op + 1) * 64 + c]);
        sWv[i] = pk2(vw[(2 * op) * 64 + c], vw[(2 * op + 1) * 64 + c]);
        sWq[i] = pk2(qw[(2 * op) * 64 + c], qw[(2 * op + 1) * 64 + c]);
    }
    for (int i = tid; i < 32 * 8; i += 128) {       // sD1[in*8 + opair]
        int in = i >> 3, op = i & 7;
        sD1[i] = pk2(d1w[(2 * op) * 32 + in], d1w[(2 * op + 1) * 32 + in]);
    }
    if (tid < 16 * 4) {                              // sD2[in*4 + opair]
        int in = tid >> 2, op = tid & 3;
        sD2[tid] = pk2(d2w[(2 * op) * 16 + in], d2w[(2 * op + 1) * 16 + in]);
    }
    if (tid >= 64 && tid < 128) {                    // sD3[in*8 + opair]
        int t = tid - 64, in = t >> 3, op = t & 7;
        sD3[t] = pk2(d3w[(2 * op) * 8 + in], d3w[(2 * op + 1) * 8 + in]);
    }
    if (tid < 32) { sKb[tid] = kb[tid]; sVb[tid] = vb[tid]; sQb[tid] = qb[tid]; }
    if (tid >= 32 && tid < 48) sD3b[tid - 32] = d3b[tid - 32];

    const int g0 = blockIdx.x * 256;
    const int b  = g0 >> 16;
    const int p0 = g0 & 65535;
    const float* kvb = kv  + ((size_t)b << 22) + p0;
    const float* qpb = qin + ((size_t)b << 22) + p0;
    const float  sc  = __ldg(scp);

    u64 A[4][8], B[4][8];
#pragma unroll
    for (int j = 0; j < 4; j++)
#pragma unroll
        for (int p = 0; p < 8; p++) { A[j][p] = 0ull; B[j][p] = 0ull; }

    // ---- K phase ----
    load_tile(sX, kvb, tid);
    __syncthreads();
    proj_phase(sX, sWk, tx, ty, A);
    __syncthreads();

    // ---- Q phase ----
    load_tile(sX, qpb, tid);
    __syncthreads();
    proj_phase(sX, sWq, tx, ty, B);

    // ---- gate: att = sigmoid((k+kb)(q+qb)*sc); A <- att, B <- 0 ----
#pragma unroll
    for (int j = 0; j < 4; j++) {
        int o = ty * 8 + 2 * j;
        float kb0 = sKb[o], kb1 = sKb[o + 1];
        float qb0 = sQb[o], qb1 = sQb[o + 1];
#pragma unroll
        for (int p = 0; p < 8; p++) {
            float k0, k1, q0, q1;
            up2(A[j][p], k0, k1); up2(B[j][p], q0, q1);
            float t0 = (k0 + kb0) * (q0 + qb0) * sc;
            float t1 = (k1 + kb1) * (q1 + qb1) * sc;
            float a0 = __fdividef(1.0f, 1.0f + __expf(-t0));
            float a1 = __fdividef(1.0f, 1.0f + __expf(-t1));
            A[j][p] = pk2(a0, a1);
            B[j][p] = 0ull;
        }
    }
    __syncthreads();

    // ---- V phase (re-stream kv tile; L2-resident) ----
    load_tile(sX, kvb, tid);
    __syncthreads();
    proj_phase(sX, sWv, tx, ty, B);
    __syncthreads();

    // ---- x = att*(v+vb) -> smem exchange, pad-33 (conflict-free) ----
    float* xs = sX;
#pragma unroll
    for (int j = 0; j < 4; j++) {
        int o = ty * 8 + 2 * j;
        float vb0 = sVb[o], vb1 = sVb[o + 1];
#pragma unroll
        for (int p = 0; p < 8; p++) {
            int px = tx + 32 * p;
            float v0, v1, a0, a1;
            up2(B[j][p], v0, v1); up2(A[j][p], a0, a1);
            xs[px * 33 + o]     = a0 * (v0 + vb0);
            xs[px * 33 + o + 1] = a1 * (v1 + vb1);
        }
    }
    __syncthreads();

    // ---- tail MLP: each thread does pixels {tid, tid+128}, fused ----
    const float* xrA = xs + (size_t)tid * 33;
    const float* xrB = xs + (size_t)(tid + 128) * 33;
    float* outp = out + ((size_t)b << 20) + p0;

    // d1: 32 -> 16, relu
    u64 hA[8], hB[8];
#pragma unroll
    for (int op = 0; op < 8; op++) { hA[op] = 0ull; hB[op] = 0ull; }
#pragma unroll 8
    for (int i = 0; i < 32; i++) {
        float ta = xrA[i], tb = xrB[i];
        u64 xa = pk2(ta, ta), xb = pk2(tb, tb);
        ulonglong2 w0 = *(const ulonglong2*)(sD1 + i * 8);
        ulonglong2 w1 = *(const ulonglong2*)(sD1 + i * 8 + 2);
        ulonglong2 w2 = *(const ulonglong2*)(sD1 + i * 8 + 4);
        ulonglong2 w3 = *(const ulonglong2*)(sD1 + i * 8 + 6);
        fma2(hA[0], w0.x, xa); fma2(hB[0], w0.x, xb);
        fma2(hA[1], w0.y, xa); fma2(hB[1], w0.y, xb);
        fma2(hA[2], w1.x, xa); fma2(hB[2], w1.x, xb);
        fma2(hA[3], w1.y, xa); fma2(hB[3], w1.y, xb);
        fma2(hA[4], w2.x, xa); fma2(hB[4], w2.x, xb);
        fma2(hA[5], w2.y, xa); fma2(hB[5], w2.y, xb);
        fma2(hA[6], w3.x, xa); fma2(hB[6], w3.x, xb);
        fma2(hA[7], w3.y, xa); fma2(hB[7], w3.y, xb);
    }
    float h1A[16], h1B[16];
#pragma unroll
    for (int op = 0; op < 8; op++) {
        float l, h;
        up2(hA[op], l, h); h1A[2 * op] = fmaxf(l, 0.f); h1A[2 * op + 1] = fmaxf(h, 0.f);
        up2(hB[op], l, h); h1B[2 * op] = fmaxf(l, 0.f); h1B[2 * op + 1] = fmaxf(h, 0.f);
    }

    // d2: 16 -> 8, relu
    u64 gA[4], gB[4];
#pragma unroll
    for (int op = 0; op < 4; op++) { gA[op] = 0ull; gB[op] = 0ull; }
#pragma unroll
    for (int i = 0; i < 16; i++) {
        u64 xa = pk2(h1A[i], h1A[i]);
        u64 xb = pk2(h1B[i], h1B[i]);
        ulonglong2 w0 = *(const ulonglong2*)(sD2 + i * 4);
        ulonglong2 w1 = *(const ulonglong2*)(sD2 + i * 4 + 2);
        fma2(gA[0], w0.x, xa); fma2(gB[0], w0.x, xb);
        fma2(gA[1], w0.y, xa); fma2(gB[1], w0.y, xb);
        fma2(gA[2], w1.x, xa); fma2(gB[2], w1.x, xb);
        fma2(gA[3], w1.y, xa); fma2(gB[3], w1.y, xb);
    }
    float h2A[8], h2B[8];
#pragma unroll
    for (int op = 0; op < 4; op++) {
        float l, h;
        up2(gA[op], l, h); h2A[2 * op] = fmaxf(l, 0.f); h2A[2 * op + 1] = fmaxf(h, 0.f);
        up2(gB[op], l, h); h2B[2 * op] = fmaxf(l, 0.f); h2B[2 * op + 1] = fmaxf(h, 0.f);
    }

    // d3: 8 -> 16, bias
    u64 yA[8], yB[8];
#pragma unroll
    for (int op = 0; op < 8; op++) { yA[op] = 0ull; yB[op] = 0ull; }
#pragma unroll
    for (int i = 0; i < 8; i++) {
        u64 xa = pk2(h2A[i], h2A[i]);
        u64 xb = pk2(h2B[i], h2B[i]);
        ulonglong2 w0 = *(const ulonglong2*)(sD3 + i * 8);
        ulonglong2 w1 = *(const ulonglong2*)(sD3 + i * 8 + 2);
        ulonglong2 w2 = *(const ulonglong2*)(sD3 + i * 8 + 4);
        ulonglong2 w3 = *(const ulonglong2*)(sD3 + i * 8 + 6);
        fma2(yA[0], w0.x, xa); fma2(yB[0], w0.x, xb);
        fma2(yA[1], w0.y, xa); fma2(yB[1], w0.y, xb);
        fma2(yA[2], w1.x, xa); fma2(yB[2], w1.x, xb);
        fma2(yA[3], w1.y, xa); fma2(yB[3], w1.y, xb);
        fma2(yA[4], w2.x, xa); fma2(yB[4], w2.x, xb);
        fma2(yA[5], w2.y, xa); fma2(yB[5], w2.y, xb);
        fma2(yA[6], w3.x, xa); fma2(yB[6], w3.x, xb);
        fma2(yA[7], w3.y, xa); fma2(yB[7], w3.y, xb);
    }
#pragma unroll
    for (int op = 0; op < 8; op++) {
        int o = 2 * op;
        float l, h;
        up2(yA[op], l, h);
        outp[((size_t)o << 16) + tid]             = l + sD3b[o];
        outp[((size_t)(o + 1) << 16) + tid]       = h + sD3b[o + 1];
        up2(yB[op], l, h);
        outp[((size_t)o << 16) + tid + 128]       = l + sD3b[o];
        outp[((size_t)(o + 1) << 16) + tid + 128] = h + sD3b[o + 1];
    }
}

extern "C" void kernel_launch(void* const* d_in, const int* in_sizes, int n_in,
                              void* d_out, int out_size)
{
    const float* kv  = (const float*)d_in[0];
    const float* qin = (const float*)d_in[1];
    const float* kw  = (const float*)d_in[2];
    const float* kb  = (const float*)d_in[3];
    const float* vw  = (const float*)d_in[4];
    const float* vb  = (const float*)d_in[5];
    const float* qw  = (const float*)d_in[6];
    const float* qb  = (const float*)d_in[7];
    const float* sc  = (const float*)d_in[8];
    const float* d1w = (const float*)d_in[9];
    const float* d2w = (const float*)d_in[10];
    const float* d3w = (const float*)d_in[11];
    const float* d3b = (const float*)d_in[12];
    float* out = (float*)d_out;

    cudaFuncSetAttribute(att_fused_kernel,
                         cudaFuncAttributeMaxDynamicSharedMemorySize, SMEM_TOTAL);

    const int total_px = 16 * 256 * 256;       // 1048576
    att_fused_kernel<<<total_px / 256, 128, SMEM_TOTAL>>>(
        kv, qin, kw, kb, vw, vb, qw, qb, sc, d1w, d2w, d3w, d3b, out);
}